// round 8
// baseline (speedup 1.0000x reference)
#include <cuda_runtime.h>

typedef unsigned long long u64;

#define LH 150
#define LQ 10
#define KI 10
#define NWARP 12
#define NBLK 148
#define STRIDE (NBLK * NWARP)

// ---- packed f32x2 helpers -------------------------------------------------
__device__ __forceinline__ u64 fma2(u64 a, u64 b, u64 c) {
    u64 d;
    asm("fma.rn.f32x2 %0, %1, %2, %3;" : "=l"(d) : "l"(a), "l"(b), "l"(c));
    return d;
}
__device__ __forceinline__ u64 pack2(float lo, float hi) {
    u64 r;
    asm("mov.b64 %0, {%1, %2};" : "=l"(r) : "f"(lo), "f"(hi));
    return r;
}
__device__ __forceinline__ u64 splat2(float x) {
    u64 r;
    asm("mov.b64 %0, {%1, %1};" : "=l"(r) : "f"(x));
    return r;
}
__device__ __forceinline__ float2 unpack2(u64 p) {
    float2 v;
    asm("mov.b64 {%0, %1}, %2;" : "=f"(v.x), "=f"(v.y) : "l"(p));
    return v;
}

// Vertical-pair register stencil (proven in R7). Lane l = (y=l>>3, x=l&7)
// owns vA = v(2y,x), vB = v(2y+1,x). 10 unconditional shuffles; boundary
// zeros applied AFTER each shuffle. fv[12] = {WN,N,EN, WA,vA,EA, WB,vB,EB,
// WS,S,ES}; pixel A's tap k uses fv[k], pixel B's tap k uses fv[k+3].
__device__ __forceinline__ void stencil12f(float vA, float vB, int lane,
                                           int y0, int x0, float* fv) {
    const unsigned m = 0xffffffffu;
    float N  = __shfl_sync(m, vB, (lane + 24) & 31);
    float Sv = __shfl_sync(m, vA, (lane + 8) & 31);
    N  = y0 ? N : 0.f;            // row -1 = 0
    Sv = (y0 < 3) ? Sv : 0.f;     // row  8 = 0
    const int lw = (lane + 31) & 31, le = (lane + 1) & 31;
    float WN = __shfl_sync(m, N,  lw);
    float WA = __shfl_sync(m, vA, lw);
    float WB = __shfl_sync(m, vB, lw);
    float WS = __shfl_sync(m, Sv, lw);
    float EN = __shfl_sync(m, N,  le);
    float EA = __shfl_sync(m, vA, le);
    float EB = __shfl_sync(m, vB, le);
    float ES = __shfl_sync(m, Sv, le);
    const bool hw = (x0 != 0), he = (x0 != 7);
    fv[0] = hw ? WN : 0.f; fv[1]  = N;  fv[2]  = he ? EN : 0.f;
    fv[3] = hw ? WA : 0.f; fv[4]  = vA; fv[5]  = he ? EA : 0.f;
    fv[6] = hw ? WB : 0.f; fv[7]  = vB; fv[8]  = he ? EB : 0.f;
    fv[9] = hw ? WS : 0.f; fv[10] = Sv; fv[11] = he ? ES : 0.f;
}

// Persistent warps: grid = 148 blocks x 12 warps; each warp grid-strides over
// images, weights resident in registers across images, next image's S row
// software-prefetched. Final conv computed only for the needed A/B half
// (warp-uniform branch) = 45 FFMA2 instead of 90.
__global__ __launch_bounds__(NWARP * 32)
void vin_kernel(const float* __restrict__ S,
                const float* __restrict__ Wh,
                const float* __restrict__ bh,
                const float* __restrict__ Wr,
                const float* __restrict__ Wq,
                const float* __restrict__ w,
                const float* __restrict__ Wfc,
                float* __restrict__ out, int B) {
    __shared__ float sweff[10];
    __shared__ u64 wsh[45];    // packed transition weights {w[2c2][k], w[2c2+1][k]}
    __shared__ u64 wqsh[45];   // packed Wq, same layout
    __shared__ float sfc[80];  // Wfc[8][10]

    const int tid = threadIdx.x;
    const int warp = tid >> 5;
    const int lane = tid & 31;

    // One-time staging
    if (tid < 45) {
        const int c2 = tid / 9, k = tid % 9;
        wsh[tid] = pack2(__ldg(&w[(2 * c2) * 9 + k]),
                         __ldg(&w[(2 * c2 + 1) * 9 + k]));
    } else if (tid < 90) {
        const int t = tid - 45;
        const int c2 = t / 9, k = t % 9;
        wqsh[t] = pack2(__ldg(&Wq[(2 * c2) * 9 + k]),
                        __ldg(&Wq[(2 * c2 + 1) * 9 + k]));
    } else if (tid < 170) {
        sfc[tid - 90] = __ldg(&Wfc[tid - 90]);
    }
    // weff: collapse 150-ch hidden conv + 1x1 readout (warp j -> output j)
    if (warp < 10) {
        float acc = 0.f;
        for (int c = lane; c < LH; c += 32) {
            float x = (warp < 9) ? __ldg(&Wh[c * 9 + warp]) : __ldg(&bh[c]);
            acc = fmaf(__ldg(&Wr[c]), x, acc);
        }
#pragma unroll
        for (int off = 16; off >= 1; off >>= 1)
            acc += __shfl_xor_sync(0xffffffffu, acc, off);
        if (lane == 0) sweff[warp] = acc;
    }
    __syncthreads();

    const int y0 = lane >> 3, x0 = lane & 7;

    // Per-warp register copy of packed transition weights (broadcast LDS, once)
    u64 wp[45];
#pragma unroll
    for (int i = 0; i < 45; ++i) wp[i] = wsh[i];

    int b = blockIdx.x * NWARP + warp;
    if (b >= B) return;

    // Prefetch first image
    const float* Sb = S + (long long)b * 66;
    float xa = Sb[16 * y0 + x0];
    float xb = Sb[16 * y0 + 8 + x0];
    float fs1 = Sb[64], fs2 = Sb[65];

    while (true) {
        // Consume prefetched values; immediately issue next image's loads.
        const float cxa = xa, cxb = xb;
        const int s1i = (int)fs1, s2i = (int)fs2;
        const int bn = b + STRIDE;
        {
            const int bpre = (bn < B) ? bn : b;
            const float* Sn = S + (long long)bpre * 66;
            xa = Sn[16 * y0 + x0];
            xb = Sn[16 * y0 + 8 + x0];
            fs1 = Sn[64]; fs2 = Sn[65];
        }

        float fv[12];

        // r = conv(X, W_eff, pad=1) + b_eff
        stencil12f(cxa, cxb, lane, y0, x0, fv);
        float r0 = sweff[9], r1 = r0;
#pragma unroll
        for (int k = 0; k < 9; ++k) {
            r0 = fmaf(sweff[k], fv[k], r0);
            r1 = fmaf(sweff[k], fv[k + 3], r1);
        }

        // qr[c] = conv(r, Wq[c], pad=1)  (loop-invariant, channel-packed)
        u64 qr0p[5], qr1p[5];
        stencil12f(r0, r1, lane, y0, x0, fv);
#pragma unroll
        for (int k = 0; k < 9; ++k) {
            const u64 s0 = splat2(fv[k]);
            const u64 s1 = splat2(fv[k + 3]);
#pragma unroll
            for (int c2 = 0; c2 < 5; ++c2) {
                const u64 wq = wqsh[c2 * 9 + k];
                qr0p[c2] = (k == 0) ? fma2(wq, s0, 0ull) : fma2(wq, s0, qr0p[c2]);
                qr1p[c2] = (k == 0) ? fma2(wq, s1, 0ull) : fma2(wq, s1, qr1p[c2]);
            }
        }

        // v = max_c qr
        float vA, vB;
        {
            float2 t0 = unpack2(qr0p[0]), t1 = unpack2(qr1p[0]);
            vA = fmaxf(t0.x, t0.y); vB = fmaxf(t1.x, t1.y);
#pragma unroll
            for (int c2 = 1; c2 < 5; ++c2) {
                t0 = unpack2(qr0p[c2]); t1 = unpack2(qr1p[c2]);
                vA = fmaxf(vA, fmaxf(t0.x, t0.y));
                vB = fmaxf(vB, fmaxf(t1.x, t1.y));
            }
        }

        // K-1 = 9 sweeps: v <- max_c( qr[c] + conv(v, w[c]) )
#pragma unroll 1
        for (int it = 0; it < KI - 1; ++it) {
            stencil12f(vA, vB, lane, y0, x0, fv);
            u64 a0[5], a1[5];
#pragma unroll
            for (int k = 0; k < 9; ++k) {
                const u64 s0 = splat2(fv[k]);
                const u64 s1 = splat2(fv[k + 3]);
#pragma unroll
                for (int c2 = 0; c2 < 5; ++c2) {
                    const u64 wk = wp[c2 * 9 + k];
                    a0[c2] = (k == 0) ? fma2(wk, s0, qr0p[c2])
                                      : fma2(wk, s0, a0[c2]);
                    a1[c2] = (k == 0) ? fma2(wk, s1, qr1p[c2])
                                      : fma2(wk, s1, a1[c2]);
                }
            }
            float2 t0 = unpack2(a0[0]), t1 = unpack2(a1[0]);
            float m0 = fmaxf(t0.x, t0.y), m1 = fmaxf(t1.x, t1.y);
#pragma unroll
            for (int c2 = 1; c2 < 5; ++c2) {
                t0 = unpack2(a0[c2]); t1 = unpack2(a1[c2]);
                m0 = fmaxf(m0, fmaxf(t0.x, t0.y));
                m1 = fmaxf(m1, fmaxf(t1.x, t1.y));
            }
            vA = m0; vB = m1;
        }

        // Final q only for the half containing the selected pixel
        // (s1i parity is per-image => warp-uniform branch). 45 FFMA2.
        stencil12f(vA, vB, lane, y0, x0, fv);
        u64 acc[5];
        if (s1i & 1) {      // pixel in B half: taps fv[k+3], base qr1p
#pragma unroll
            for (int k = 0; k < 9; ++k) {
                const u64 s1 = splat2(fv[k + 3]);
#pragma unroll
                for (int c2 = 0; c2 < 5; ++c2)
                    acc[c2] = (k == 0) ? fma2(wp[c2 * 9], s1, qr1p[c2])
                                       : fma2(wp[c2 * 9 + k], s1, acc[c2]);
            }
        } else {            // pixel in A half: taps fv[k], base qr0p
#pragma unroll
            for (int k = 0; k < 9; ++k) {
                const u64 s0 = splat2(fv[k]);
#pragma unroll
                for (int c2 = 0; c2 < 5; ++c2)
                    acc[c2] = (k == 0) ? fma2(wp[c2 * 9], s0, qr0p[c2])
                                       : fma2(wp[c2 * 9 + k], s0, acc[c2]);
            }
        }

        // Selected pixel (s1=row, s2=col) lives in lane (s1>>1)*8 + s2.
        const int lsel = (s1i >> 1) * 8 + s2i;
        if (lane == lsel) {
            float lg[8];
#pragma unroll
            for (int j = 0; j < 8; ++j) lg[j] = 0.f;
#pragma unroll
            for (int c2 = 0; c2 < 5; ++c2) {
                const float2 q = unpack2(acc[c2]);
#pragma unroll
                for (int j = 0; j < 8; ++j) {
                    lg[j] = fmaf(q.x, sfc[j * 10 + 2 * c2], lg[j]);
                    lg[j] = fmaf(q.y, sfc[j * 10 + 2 * c2 + 1], lg[j]);
                }
            }
            float4* o4 = (float4*)(out + (long long)b * 8);
            o4[0] = make_float4(lg[0], lg[1], lg[2], lg[3]);
            o4[1] = make_float4(lg[4], lg[5], lg[6], lg[7]);
        }

        if (bn >= B) break;
        b = bn;
    }
}

extern "C" void kernel_launch(void* const* d_in, const int* in_sizes, int n_in,
                              void* d_out, int out_size) {
    const float* S   = (const float*)d_in[0];
    const float* Wh  = (const float*)d_in[1];
    const float* bh  = (const float*)d_in[2];
    const float* Wr  = (const float*)d_in[3];
    const float* Wq  = (const float*)d_in[4];
    const float* w   = (const float*)d_in[5];
    const float* Wfc = (const float*)d_in[6];
    float* out = (float*)d_out;

    const int B = in_sizes[0] / 66;
    vin_kernel<<<NBLK, NWARP * 32>>>(S, Wh, bh, Wr, Wq, w, Wfc, out, B);
}

// round 9
// speedup vs baseline: 1.1605x; 1.1605x over previous
#include <cuda_runtime.h>

typedef unsigned long long u64;

#define LH 150
#define LQ 10
#define KI 10
#define NWARP 12

// ---- packed f32x2 helpers -------------------------------------------------
__device__ __forceinline__ u64 fma2(u64 a, u64 b, u64 c) {
    u64 d;
    asm("fma.rn.f32x2 %0, %1, %2, %3;" : "=l"(d) : "l"(a), "l"(b), "l"(c));
    return d;
}
__device__ __forceinline__ u64 pack2(float lo, float hi) {
    u64 r;
    asm("mov.b64 %0, {%1, %2};" : "=l"(r) : "f"(lo), "f"(hi));
    return r;
}
__device__ __forceinline__ u64 splat2(float x) {
    u64 r;
    asm("mov.b64 %0, {%1, %1};" : "=l"(r) : "f"(x));
    return r;
}
__device__ __forceinline__ float2 unpack2(u64 p) {
    float2 v;
    asm("mov.b64 {%0, %1}, %2;" : "=f"(v.x), "=f"(v.y) : "l"(p));
    return v;
}

// Vertical-pair register stencil (proven). Lane l = (y=l>>3, x=l&7) owns
// vA = v(2y,x), vB = v(2y+1,x). 10 unconditional shuffles; boundary zeros
// applied AFTER each shuffle. fv[12] = {WN,N,EN, WA,vA,EA, WB,vB,EB, WS,S,ES};
// pixel A's tap k uses fv[k], pixel B's tap k uses fv[k+3].
__device__ __forceinline__ void stencil12f(float vA, float vB, int lane,
                                           int y0, int x0, float* fv) {
    const unsigned m = 0xffffffffu;
    float N  = __shfl_sync(m, vB, (lane + 24) & 31);
    float Sv = __shfl_sync(m, vA, (lane + 8) & 31);
    N  = y0 ? N : 0.f;            // row -1 = 0
    Sv = (y0 < 3) ? Sv : 0.f;     // row  8 = 0
    const int lw = (lane + 31) & 31, le = (lane + 1) & 31;
    float WN = __shfl_sync(m, N,  lw);
    float WA = __shfl_sync(m, vA, lw);
    float WB = __shfl_sync(m, vB, lw);
    float WS = __shfl_sync(m, Sv, lw);
    float EN = __shfl_sync(m, N,  le);
    float EA = __shfl_sync(m, vA, le);
    float EB = __shfl_sync(m, vB, le);
    float ES = __shfl_sync(m, Sv, le);
    const bool hw = (x0 != 0), he = (x0 != 7);
    fv[0] = hw ? WN : 0.f; fv[1]  = N;  fv[2]  = he ? EN : 0.f;
    fv[3] = hw ? WA : 0.f; fv[4]  = vA; fv[5]  = he ? EA : 0.f;
    fv[6] = hw ? WB : 0.f; fv[7]  = vB; fv[8]  = he ? EB : 0.f;
    fv[9] = hw ? WS : 0.f; fv[10] = Sv; fv[11] = he ? ES : 0.f;
}

// One warp per batch element (R7 launch shape — hardware load balancing).
// Fully register-resident iteration loop; channel-paired weights in 90 regs.
// Final conv round computes only the warp-uniform A-or-B half (45 FFMA2).
__global__ __launch_bounds__(NWARP * 32)
void vin_kernel(const float* __restrict__ S,
                const float* __restrict__ Wh,
                const float* __restrict__ bh,
                const float* __restrict__ Wr,
                const float* __restrict__ Wq,
                const float* __restrict__ w,
                const float* __restrict__ Wfc,
                float* __restrict__ out, int B) {
    __shared__ float sweff[10];
    __shared__ u64 wsh[45];    // packed transition weights {w[2c2][k], w[2c2+1][k]}
    __shared__ u64 wqsh[45];   // packed Wq, same layout
    __shared__ float sfc[80];  // Wfc[8][10]

    const int tid = threadIdx.x;
    const int warp = tid >> 5;
    const int lane = tid & 31;

    // One-time staging of packed weights + FC head
    if (tid < 45) {
        const int c2 = tid / 9, k = tid % 9;
        wsh[tid] = pack2(__ldg(&w[(2 * c2) * 9 + k]),
                         __ldg(&w[(2 * c2 + 1) * 9 + k]));
    } else if (tid < 90) {
        const int t = tid - 45;
        const int c2 = t / 9, k = t % 9;
        wqsh[t] = pack2(__ldg(&Wq[(2 * c2) * 9 + k]),
                        __ldg(&Wq[(2 * c2 + 1) * 9 + k]));
    } else if (tid < 170) {
        sfc[tid - 90] = __ldg(&Wfc[tid - 90]);
    }
    // weff: collapse 150-ch hidden conv + 1x1 readout (warp j -> output j)
    if (warp < 10) {
        float acc = 0.f;
        for (int c = lane; c < LH; c += 32) {
            float x = (warp < 9) ? __ldg(&Wh[c * 9 + warp]) : __ldg(&bh[c]);
            acc = fmaf(__ldg(&Wr[c]), x, acc);
        }
#pragma unroll
        for (int off = 16; off >= 1; off >>= 1)
            acc += __shfl_xor_sync(0xffffffffu, acc, off);
        if (lane == 0) sweff[warp] = acc;
    }
    __syncthreads();

    const int b = blockIdx.x * NWARP + warp;
    if (b >= B) return;                    // warp-uniform; no syncs below
    const float* Sb = S + (long long)b * 66;

    const int y0 = lane >> 3, x0 = lane & 7;

    // Per-warp register copy of packed transition weights (broadcast LDS, once)
    u64 wp[45];
#pragma unroll
    for (int i = 0; i < 45; ++i) wp[i] = wsh[i];

    // X in registers: vA = row 2y, vB = row 2y+1 of column x
    float vA = Sb[16 * y0 + x0];
    float vB = Sb[16 * y0 + 8 + x0];
    const int s1i = (int)Sb[64];
    const int s2i = (int)Sb[65];

    float fv[12];

    // r = conv(X, W_eff, pad=1) + b_eff
    stencil12f(vA, vB, lane, y0, x0, fv);
    float r0 = sweff[9], r1 = r0;
#pragma unroll
    for (int k = 0; k < 9; ++k) {
        r0 = fmaf(sweff[k], fv[k], r0);
        r1 = fmaf(sweff[k], fv[k + 3], r1);
    }

    // qr[c] = conv(r, Wq[c], pad=1)  (loop-invariant, channel-packed)
    u64 qr0p[5], qr1p[5];
    stencil12f(r0, r1, lane, y0, x0, fv);
#pragma unroll
    for (int k = 0; k < 9; ++k) {
        const u64 s0 = splat2(fv[k]);
        const u64 s1 = splat2(fv[k + 3]);
#pragma unroll
        for (int c2 = 0; c2 < 5; ++c2) {
            const u64 wq = wqsh[c2 * 9 + k];          // broadcast LDS, one-time
            qr0p[c2] = (k == 0) ? fma2(wq, s0, 0ull) : fma2(wq, s0, qr0p[c2]);
            qr1p[c2] = (k == 0) ? fma2(wq, s1, 0ull) : fma2(wq, s1, qr1p[c2]);
        }
    }

    // v = max_c qr
    {
        float2 t0 = unpack2(qr0p[0]), t1 = unpack2(qr1p[0]);
        vA = fmaxf(t0.x, t0.y); vB = fmaxf(t1.x, t1.y);
#pragma unroll
        for (int c2 = 1; c2 < 5; ++c2) {
            t0 = unpack2(qr0p[c2]); t1 = unpack2(qr1p[c2]);
            vA = fmaxf(vA, fmaxf(t0.x, t0.y));
            vB = fmaxf(vB, fmaxf(t1.x, t1.y));
        }
    }

    // K-1 = 9 sweeps: v <- max_c( qr[c] + conv(v, w[c]) ), all in registers
#pragma unroll 1
    for (int it = 0; it < KI - 1; ++it) {
        stencil12f(vA, vB, lane, y0, x0, fv);
        u64 a0[5], a1[5];
#pragma unroll
        for (int k = 0; k < 9; ++k) {
            const u64 s0 = splat2(fv[k]);
            const u64 s1 = splat2(fv[k + 3]);
#pragma unroll
            for (int c2 = 0; c2 < 5; ++c2) {
                const u64 wk = wp[c2 * 9 + k];
                a0[c2] = (k == 0) ? fma2(wk, s0, qr0p[c2])
                                  : fma2(wk, s0, a0[c2]);
                a1[c2] = (k == 0) ? fma2(wk, s1, qr1p[c2])
                                  : fma2(wk, s1, a1[c2]);
            }
        }
        float2 t0 = unpack2(a0[0]), t1 = unpack2(a1[0]);
        float m0 = fmaxf(t0.x, t0.y), m1 = fmaxf(t1.x, t1.y);
#pragma unroll
        for (int c2 = 1; c2 < 5; ++c2) {
            t0 = unpack2(a0[c2]); t1 = unpack2(a1[c2]);
            m0 = fmaxf(m0, fmaxf(t0.x, t0.y));
            m1 = fmaxf(m1, fmaxf(t1.x, t1.y));
        }
        vA = m0; vB = m1;
    }

    // Final q only for the half containing the selected pixel
    // (s1 parity is per-image => warp-uniform branch). 45 FFMA2.
    stencil12f(vA, vB, lane, y0, x0, fv);
    u64 acc[5];
    if (s1i & 1) {      // pixel in B half: taps fv[k+3], base qr1p
#pragma unroll
        for (int k = 0; k < 9; ++k) {
            const u64 s1 = splat2(fv[k + 3]);
#pragma unroll
            for (int c2 = 0; c2 < 5; ++c2)
                acc[c2] = (k == 0) ? fma2(wp[c2 * 9], s1, qr1p[c2])
                                   : fma2(wp[c2 * 9 + k], s1, acc[c2]);
        }
    } else {            // pixel in A half: taps fv[k], base qr0p
#pragma unroll
        for (int k = 0; k < 9; ++k) {
            const u64 s0 = splat2(fv[k]);
#pragma unroll
            for (int c2 = 0; c2 < 5; ++c2)
                acc[c2] = (k == 0) ? fma2(wp[c2 * 9], s0, qr0p[c2])
                                   : fma2(wp[c2 * 9 + k], s0, acc[c2]);
        }
    }

    // Selected pixel (s1=row, s2=col) lives in lane (s1>>1)*8 + s2.
    const int lsel = (s1i >> 1) * 8 + s2i;
    if (lane == lsel) {
        float lg[8];
#pragma unroll
        for (int j = 0; j < 8; ++j) lg[j] = 0.f;
#pragma unroll
        for (int c2 = 0; c2 < 5; ++c2) {
            const float2 q = unpack2(acc[c2]);
#pragma unroll
            for (int j = 0; j < 8; ++j) {
                lg[j] = fmaf(q.x, sfc[j * 10 + 2 * c2], lg[j]);
                lg[j] = fmaf(q.y, sfc[j * 10 + 2 * c2 + 1], lg[j]);
            }
        }
        float4* o4 = (float4*)(out + (long long)b * 8);
        o4[0] = make_float4(lg[0], lg[1], lg[2], lg[3]);
        o4[1] = make_float4(lg[4], lg[5], lg[6], lg[7]);
    }
}

extern "C" void kernel_launch(void* const* d_in, const int* in_sizes, int n_in,
                              void* d_out, int out_size) {
    const float* S   = (const float*)d_in[0];
    const float* Wh  = (const float*)d_in[1];
    const float* bh  = (const float*)d_in[2];
    const float* Wr  = (const float*)d_in[3];
    const float* Wq  = (const float*)d_in[4];
    const float* w   = (const float*)d_in[5];
    const float* Wfc = (const float*)d_in[6];
    float* out = (float*)d_out;

    const int B = in_sizes[0] / 66;
    const int grid = (B + NWARP - 1) / NWARP;
    vin_kernel<<<grid, NWARP * 32>>>(S, Wh, bh, Wr, Wq, w, Wfc, out, B);
}